// round 7
// baseline (speedup 1.0000x reference)
#include <cuda_runtime.h>
#include <math.h>

#define Bq 4
#define Sq 4096
#define Hq 1024
#define NHq 16
#define Dq 64
#define SCALEq 0.125f
#define NBLK 132
#define NTHR 256
#define SMEM_BYTES 73856

typedef unsigned long long ull;
typedef unsigned int uint;

// scratch (no allocation allowed)
__device__ float g_cnt[Bq*Sq*2];         // [b][s] float2 (r0,r1)
__device__ float g_xsum[Bq*2*Hq];
__device__ float g_t[Bq*Hq];             // (xsum0-xsum1) @ Wk
__device__ float g_vsum[Bq*2*Hq];
__device__ float g_pdiff[Bq*NHq*Hq];
__device__ float g_bdiff[Bq*NHq];
__device__ uint  g_barcnt[4];            // zero-init; returns to 0 after each use
__device__ uint  g_bargen[4];            // monotone generation (wrap-safe compare)

// ---- grid barrier: safe because all NBLK<=SMs blocks are co-resident (occ 1) ----
__device__ __forceinline__ void gridbar(int i) {
    __syncthreads();
    __threadfence();
    if (threadIdx.x == 0) {
        uint g = *((volatile uint*)&g_bargen[i]);
        uint old = atomicAdd(&g_barcnt[i], 1u);
        if (old == NBLK - 1) {
            g_barcnt[i] = 0;
            __threadfence();
            atomicAdd(&g_bargen[i], 1u);
        } else {
            while (*((volatile uint*)&g_bargen[i]) == g) { }
        }
    }
    __syncthreads();
}

// ---- packed f32x2 helpers ----
__device__ __forceinline__ ull pk(float lo, float hi) {
    ull r; asm("mov.b64 %0, {%1, %2};" : "=l"(r) : "f"(lo), "f"(hi)); return r;
}
__device__ __forceinline__ void fma2(ull& a, ull x, ull y) {
    asm("fma.rn.f32x2 %0, %1, %2, %0;" : "+l"(a) : "l"(x), "l"(y));
}
__device__ __forceinline__ ull add2(ull a, ull b) {
    ull r; asm("add.rn.f32x2 %0, %1, %2;" : "=l"(r) : "l"(a), "l"(b)); return r;
}
__device__ __forceinline__ ull shfl2x(ull v, int m) {
    uint lo = (uint)v, hi = (uint)(v >> 32);
    lo = __shfl_xor_sync(0xffffffffu, lo, m);
    hi = __shfl_xor_sync(0xffffffffu, hi, m);
    return ((ull)hi << 32) | (ull)lo;
}
__device__ __forceinline__ float ull_lo(ull v) { return __uint_as_float((uint)v); }
__device__ __forceinline__ float ull_hi(ull v) { return __uint_as_float((uint)(v >> 32)); }
__device__ __forceinline__ float d_lo(double d) { return __uint_as_float((uint)__double_as_longlong(d)); }
__device__ __forceinline__ float d_hi(double d) { return __uint_as_float((uint)(__double_as_longlong(d) >> 32)); }

__global__ __launch_bounds__(NTHR)
void kfused(const float* __restrict__ x, const int* __restrict__ idx,
            const float* __restrict__ Wq, const float* __restrict__ bq,
            const float* __restrict__ Wk, const float* __restrict__ Wv,
            const float* __restrict__ bv, float* __restrict__ out) {
    extern __shared__ char smem[];
    int bid = blockIdx.x, tid = threadIdx.x;

    // ================= phase 1: histogram + zero g_xsum =================
    if (bid < Bq) {
        int b = bid;
        int* sh0 = (int*)smem;            // 16KB
        int* sh1 = sh0 + Sq;              // 16KB
        for (int j = tid; j < Sq; j += NTHR) { sh0[j] = 0; sh1[j] = 0; }
        __syncthreads();
        const int2* ip = (const int2*)(idx + (size_t)b * Sq * 2);
        for (int s = tid; s < Sq; s += NTHR) {
            int2 p = ip[s];
            atomicAdd(&sh0[p.x], 1);
            atomicAdd(&sh1[p.y], 1);
        }
        __syncthreads();
        float2* c2 = (float2*)g_cnt + b * Sq;
        for (int j = tid; j < Sq; j += NTHR)
            c2[j] = make_float2((float)sh0[j], (float)sh1[j]);
    } else if (bid < 8) {
        int k = bid - 4;
        for (int i = tid; i < 2048; i += NTHR) g_xsum[k * 2048 + i] = 0.f;
    }
    gridbar(0);

    // ================= phase 2: xsum[b,r,:] = sum_s cnt[b,s,r]*x[b,s,:] =================
    // 296 units: (b, 56-row chunk)
    for (int u = bid; u < 296; u += NBLK) {
        int b = u & 3, chunk = u >> 2;
        int s0 = chunk * 56;
        int ns = (Sq - s0 < 56) ? (Sq - s0) : 56;
        const float2* cnt2 = (const float2*)g_cnt + b * Sq;
        const float4* xb4 = (const float4*)(x + (size_t)b * Sq * Hq);
        float4 a0 = make_float4(0.f,0.f,0.f,0.f);
        float4 a1 = make_float4(0.f,0.f,0.f,0.f);
        #pragma unroll 4
        for (int s = s0; s < s0 + ns; s++) {
            float2 c = cnt2[s];
            float4 xv = xb4[(size_t)s * 256 + tid];
            a0.x += c.x*xv.x; a0.y += c.x*xv.y; a0.z += c.x*xv.z; a0.w += c.x*xv.w;
            a1.x += c.y*xv.x; a1.y += c.y*xv.y; a1.z += c.y*xv.z; a1.w += c.y*xv.w;
        }
        float* o0 = &g_xsum[(b*2 + 0)*Hq + tid*4];
        float* o1 = &g_xsum[(b*2 + 1)*Hq + tid*4];
        atomicAdd(o0+0, a0.x); atomicAdd(o0+1, a0.y); atomicAdd(o0+2, a0.z); atomicAdd(o0+3, a0.w);
        atomicAdd(o1+0, a1.x); atomicAdd(o1+1, a1.y); atomicAdd(o1+2, a1.z); atomicAdd(o1+3, a1.w);
    }
    gridbar(1);

    // ================= phase 3: t = xd@Wk ; vsum = xsum@Wv + S*bv (atomic-free) =================
    if (bid < 32) {
        // t-unit: 32 output cols, sum over all 1024 input rows
        float* sxd = (float*)smem;                    // [4][1024] 16KB
        float* sred = (float*)(smem + 49152);         // [8][32][4]
        for (int i = tid; i < Bq*Hq; i += NTHR) {
            int b = i >> 10, hc = i & (Hq-1);
            sxd[i] = g_xsum[(b*2 + 0)*Hq + hc] - g_xsum[(b*2 + 1)*Hq + hc];
        }
        __syncthreads();
        int c = tid & 31, q = tid >> 5;               // q 0..7
        int col = bid * 32 + c;
        const float* Wp = Wk + (size_t)(q*128) * Hq + col;
        float a[4] = {0.f,0.f,0.f,0.f};
        #pragma unroll 8
        for (int hc = 0; hc < 128; hc++) {
            float w = Wp[(size_t)hc * Hq];
            int g = q*128 + hc;
            a[0] += sxd[g]*w; a[1] += sxd[Hq+g]*w; a[2] += sxd[2*Hq+g]*w; a[3] += sxd[3*Hq+g]*w;
        }
        #pragma unroll
        for (int b = 0; b < 4; b++) sred[(q*32 + c)*4 + b] = a[b];
        __syncthreads();
        if (q == 0) {
            #pragma unroll
            for (int b = 0; b < 4; b++) {
                float s = 0.f;
                #pragma unroll
                for (int qq = 0; qq < 8; qq++) s += sred[(qq*32 + c)*4 + b];
                g_t[b*Hq + col] = s;
            }
        }
    } else if (bid < 64) {
        // vsum-unit: 32 output cols
        float* sxs = (float*)smem;                    // [8][1024] 32KB
        float* sred = (float*)(smem + 49152);         // [8][32][8]
        for (int i = tid; i < 8*Hq; i += NTHR) sxs[i] = g_xsum[i];
        __syncthreads();
        int c = tid & 31, q = tid >> 5;
        int col = (bid - 32) * 32 + c;
        const float* Wp = Wv + (size_t)(q*128) * Hq + col;
        float a[8] = {0.f,0.f,0.f,0.f,0.f,0.f,0.f,0.f};
        #pragma unroll 8
        for (int hc = 0; hc < 128; hc++) {
            float w = Wp[(size_t)hc * Hq];
            int g = q*128 + hc;
            #pragma unroll
            for (int br = 0; br < 8; br++) a[br] += sxs[br*Hq + g]*w;
        }
        #pragma unroll
        for (int br = 0; br < 8; br++) sred[(q*32 + c)*8 + br] = a[br];
        __syncthreads();
        if (q == 0) {
            float bias = 4096.f * bv[col];
            #pragma unroll
            for (int br = 0; br < 8; br++) {
                float s = 0.f;
                #pragma unroll
                for (int qq = 0; qq < 8; qq++) s += sred[(qq*32 + c)*8 + br];
                g_vsum[br*Hq + col] = s + bias;
            }
        }
    }
    gridbar(2);

    // ================= phase 4: pdiff / bdiff (warp-per-Wq-row) =================
    {
        float* st = (float*)smem;                     // [4][1024] 16KB
        for (int i = tid; i < Bq*Hq; i += NTHR) st[i] = g_t[i];
        __syncthreads();
        int warp = tid >> 5, lane = tid & 31;
        for (int wg = bid*8 + warp; wg < 1024 + Bq*NHq; wg += NBLK*8) {
            if (wg < 1024) {
                int h = wg;
                const float4* wr = (const float4*)(Wq + (size_t)h * Hq);
                float4 w[8];
                #pragma unroll
                for (int j = 0; j < 8; j++) w[j] = wr[j*32 + lane];
                float acc[Bq][8];
                #pragma unroll
                for (int b = 0; b < Bq; b++) {
                    const float4* tb = (const float4*)&st[b*Hq];
                    #pragma unroll
                    for (int j = 0; j < 8; j++) {
                        float4 tv = tb[j*32 + lane];
                        acc[b][j] = w[j].x*tv.x + w[j].y*tv.y + w[j].z*tv.z + w[j].w*tv.w;
                    }
                }
                #pragma unroll
                for (int b = 0; b < Bq; b++)
                    #pragma unroll
                    for (int j = 0; j < 8; j++) {
                        float v = acc[b][j];
                        v += __shfl_xor_sync(0xffffffffu, v, 8);
                        v += __shfl_xor_sync(0xffffffffu, v, 4);
                        v += __shfl_xor_sync(0xffffffffu, v, 2);
                        v += __shfl_xor_sync(0xffffffffu, v, 1);
                        acc[b][j] = v;
                    }
                if ((lane & 15) == 0) {
                    int half = lane >> 4;
                    #pragma unroll
                    for (int b = 0; b < Bq; b++)
                        #pragma unroll
                        for (int j = 0; j < 8; j++)
                            g_pdiff[(b*NHq + (2*j + half))*Hq + h] = SCALEq * acc[b][j];
                }
            } else {
                int id = wg - 1024;
                int b = id >> 4, n = id & 15;
                float s = bq[n*Dq + lane]      * st[b*Hq + n*Dq + lane]
                        + bq[n*Dq + 32 + lane] * st[b*Hq + n*Dq + 32 + lane];
                #pragma unroll
                for (int o = 16; o > 0; o >>= 1) s += __shfl_xor_sync(0xffffffffu, s, o);
                if (lane == 0) g_bdiff[b*NHq + n] = SCALEq * s;
            }
        }
    }
    gridbar(3);

    // ================= phase 5: scores (row-pair f32x2) -> sigmoid -> blend =================
    {
        float* sPd = (float*)smem;                    // [16][1024] 64KB
        float* sV0 = sPd + NHq*Hq;                    // [1024]
        float* sV1 = sV0 + Hq;                        // [1024]
        float* sBd = sV1 + Hq;                        // [16]
        int b = bid / 33;
        int local = bid % 33;
        {
            const float4* gp4 = (const float4*)&g_pdiff[b*NHq*Hq];
            float4* sp4 = (float4*)sPd;
            for (int i = tid; i < NHq*Hq/4; i += NTHR) sp4[i] = gp4[i];
            const float4* v0g = (const float4*)&g_vsum[(b*2 + 0)*Hq];
            const float4* v1g = (const float4*)&g_vsum[(b*2 + 1)*Hq];
            float4* s04 = (float4*)sV0; float4* s14 = (float4*)sV1;
            for (int i = tid; i < Hq/4; i += NTHR) { s04[i] = v0g[i]; s14[i] = v1g[i]; }
            if (tid < NHq) sBd[tid] = g_bdiff[b*NHq + tid];
        }
        __syncthreads();

        int warp = tid >> 5, lane = tid & 31;
        int half = lane >> 4;
        const float* xb = x + (size_t)b * Sq * Hq;
        float* ob = out + (size_t)b * Sq * Hq;
        const float4* sPd4 = (const float4*)sPd;
        const float4* v04 = (const float4*)sV0;
        const float4* v14 = (const float4*)sV1;
        float bdl[8];
        #pragma unroll
        for (int j = 0; j < 8; j++) bdl[j] = sBd[2*j + half];

        for (int t = local; t < 64; t += 33) {        // 64 rows/tile: 8 warps x 8 rows
            int r0 = t*64 + warp*8;
            const double2* xr = (const double2*)(xb + (size_t)r0 * Hq);

            ull acc[4][NHq];
            #pragma unroll
            for (int i = 0; i < 4; i++)
                #pragma unroll
                for (int n = 0; n < NHq; n++) acc[i][n] = 0ull;

            double2 cur[8];
            #pragma unroll
            for (int i = 0; i < 8; i++) cur[i] = xr[i*256 + lane];

            #pragma unroll
            for (int j = 0; j < 8; j++) {
                int h4 = lane + 32*j;
                // pack row-pairs (i, i+4) per float component
                ull xp[4][4];
                #pragma unroll
                for (int i = 0; i < 4; i++) {
                    xp[i][0] = pk(d_lo(cur[i].x), d_lo(cur[i+4].x));
                    xp[i][1] = pk(d_hi(cur[i].x), d_hi(cur[i+4].x));
                    xp[i][2] = pk(d_lo(cur[i].y), d_lo(cur[i+4].y));
                    xp[i][3] = pk(d_hi(cur[i].y), d_hi(cur[i+4].y));
                }
                if (j < 7) {
                    #pragma unroll
                    for (int i = 0; i < 8; i++) cur[i] = xr[i*256 + h4 + 32];
                }
                #pragma unroll
                for (int n = 0; n < NHq; n++) {
                    float4 pd = sPd4[n*256 + h4];
                    ull p0 = pk(pd.x, pd.x), p1 = pk(pd.y, pd.y);
                    ull p2 = pk(pd.z, pd.z), p3 = pk(pd.w, pd.w);
                    #pragma unroll
                    for (int i = 0; i < 4; i++) {
                        fma2(acc[i][n], xp[i][0], p0);
                        fma2(acc[i][n], xp[i][1], p1);
                        fma2(acc[i][n], xp[i][2], p2);
                        fma2(acc[i][n], xp[i][3], p3);
                    }
                }
            }

            // packed butterfly reduction (each ull = scores of rows i and i+4)
            #pragma unroll
            for (int i = 0; i < 4; i++)
                #pragma unroll
                for (int n = 0; n < NHq; n++) {
                    ull v = acc[i][n];
                    v = add2(v, shfl2x(v, 16));
                    v = add2(v, shfl2x(v, 8));
                    v = add2(v, shfl2x(v, 4));
                    v = add2(v, shfl2x(v, 2));
                    v = add2(v, shfl2x(v, 1));
                    acc[i][n] = v;
                }

            // blend + store (per lane: head n = 2j + half at column group h4)
            #pragma unroll
            for (int i = 0; i < 8; i++) {
                float4* o4 = (float4*)(ob + (size_t)(r0 + i) * Hq);
                #pragma unroll
                for (int j = 0; j < 8; j++) {
                    int h4 = lane + 32*j;
                    ull v = acc[i & 3][2*j + half];
                    float s = (i < 4) ? ull_lo(v) : ull_hi(v);
                    float pp = 1.f / (1.f + __expf(-(s + bdl[j])));
                    float4 a = v04[h4];
                    float4 c = v14[h4];
                    float4 o;
                    o.x = c.x + pp * (a.x - c.x);
                    o.y = c.y + pp * (a.y - c.y);
                    o.z = c.z + pp * (a.z - c.z);
                    o.w = c.w + pp * (a.w - c.w);
                    o4[h4] = o;
                }
            }
        }
    }
}

extern "C" void kernel_launch(void* const* d_in, const int* in_sizes, int n_in,
                              void* d_out, int out_size) {
    const float* x  = (const float*)d_in[0];
    // d_in[1] attention_mask: unused by reference
    const float* Wq = (const float*)d_in[2];
    const float* bq = (const float*)d_in[3];
    const float* Wk = (const float*)d_in[4];
    // d_in[5] bk cancels in the score difference
    const float* Wv = (const float*)d_in[6];
    const float* bv = (const float*)d_in[7];
    const int* idx  = (const int*)d_in[8];
    float* out = (float*)d_out;

    cudaFuncSetAttribute(kfused, cudaFuncAttributeMaxDynamicSharedMemorySize, SMEM_BYTES);
    kfused<<<NBLK, NTHR, SMEM_BYTES>>>(x, idx, Wq, bq, Wk, Wv, bv, out);
}

// round 11
// speedup vs baseline: 2.1042x; 2.1042x over previous
#include <cuda_runtime.h>
#include <math.h>

#define Bq 4
#define Sq 4096
#define Hq 1024
#define NHq 16
#define Dq 64
#define Rq 2
#define SCALEq 0.125f

// scratch (no allocation allowed)
__device__ float g_cnt[Bq*Sq*2];         // [b][s] float2 (r0,r1)
__device__ float g_xsum[Bq*Rq*Hq];
__device__ float g_t[Bq*Hq];             // (xsum0-xsum1) @ Wk
__device__ float g_vsum[Bq*Rq*Hq];
__device__ float g_pdiff[Bq*NHq*Hq];
__device__ float g_bdiff[Bq*NHq];

// ================= k_hist: per-b histogram of both r + buffer init =================
__global__ void __launch_bounds__(512)
k_hist(const int* __restrict__ idx, const float* __restrict__ bv) {
    __shared__ int sh0[Sq];              // 16KB
    __shared__ int sh1[Sq];              // 16KB
    int b = blockIdx.x, tid = threadIdx.x;
    for (int j = tid; j < Sq; j += 512) { sh0[j] = 0; sh1[j] = 0; }
    for (int i = tid; i < Hq; i += 512) {
        g_xsum[(b*Rq + 0)*Hq + i] = 0.f;
        g_xsum[(b*Rq + 1)*Hq + i] = 0.f;
        g_t[b*Hq + i] = 0.f;
        float sv = 4096.f * bv[i];
        g_vsum[(b*Rq + 0)*Hq + i] = sv;
        g_vsum[(b*Rq + 1)*Hq + i] = sv;
    }
    __syncthreads();
    const int2* ip = (const int2*)(idx + (size_t)b * Sq * Rq);
    for (int s = tid; s < Sq; s += 512) {
        int2 p = ip[s];
        atomicAdd(&sh0[p.x], 1);
        atomicAdd(&sh1[p.y], 1);
    }
    __syncthreads();
    float2* c2 = (float2*)g_cnt + b*Sq;
    for (int j = tid; j < Sq; j += 512)
        c2[j] = make_float2((float)sh0[j], (float)sh1[j]);
}

// ================= k_xsum: xsum[b,r,:] = sum_s cnt[b,s,r]*x[b,s,:] =================
#define SCHUNKS 64
#define SROWS (Sq / SCHUNKS)             // 64
__global__ void __launch_bounds__(256)
k_xsum(const float* __restrict__ x) {
    int b = blockIdx.y, tid = threadIdx.x;
    int s0 = blockIdx.x * SROWS;
    const float2* cnt2 = (const float2*)g_cnt + b*Sq;
    const float4* xb4 = (const float4*)(x + (size_t)b * Sq * Hq);
    float4 a0 = make_float4(0.f,0.f,0.f,0.f);
    float4 a1 = make_float4(0.f,0.f,0.f,0.f);
    #pragma unroll 8
    for (int s = s0; s < s0 + SROWS; s++) {
        float2 c = cnt2[s];
        float4 xv = xb4[(size_t)s * 256 + tid];
        a0.x += c.x*xv.x; a0.y += c.x*xv.y; a0.z += c.x*xv.z; a0.w += c.x*xv.w;
        a1.x += c.y*xv.x; a1.y += c.y*xv.y; a1.z += c.y*xv.z; a1.w += c.y*xv.w;
    }
    float* o0 = &g_xsum[(b*Rq + 0)*Hq + tid*4];
    float* o1 = &g_xsum[(b*Rq + 1)*Hq + tid*4];
    atomicAdd(o0+0, a0.x); atomicAdd(o0+1, a0.y); atomicAdd(o0+2, a0.z); atomicAdd(o0+3, a0.w);
    atomicAdd(o1+0, a1.x); atomicAdd(o1+1, a1.y); atomicAdd(o1+2, a1.z); atomicAdd(o1+3, a1.w);
}

// ================= k_proj: t = xd@Wk (y=0) ; vsum += xsum@Wv (y=1) =================
__global__ void __launch_bounds__(256)
k_proj(const float* __restrict__ Wk, const float* __restrict__ Wv) {
    __shared__ float xa[16][8];
    int tid = threadIdx.x;
    int hc = blockIdx.x * 16;
    if (blockIdx.y == 0) {
        if (tid < 64) {
            int hl = tid >> 2, b = tid & 3;
            xa[hl][b] = g_xsum[(b*Rq + 0)*Hq + hc + hl] - g_xsum[(b*Rq + 1)*Hq + hc + hl];
        }
        __syncthreads();
        float4 acc[4];
        #pragma unroll
        for (int b = 0; b < 4; b++) acc[b] = make_float4(0.f,0.f,0.f,0.f);
        const float4* W4 = (const float4*)Wk;
        #pragma unroll
        for (int hl = 0; hl < 16; hl++) {
            float4 w = W4[(size_t)(hc + hl) * 256 + tid];
            #pragma unroll
            for (int b = 0; b < 4; b++) {
                float xv = xa[hl][b];
                acc[b].x += xv*w.x; acc[b].y += xv*w.y; acc[b].z += xv*w.z; acc[b].w += xv*w.w;
            }
        }
        #pragma unroll
        for (int b = 0; b < 4; b++) {
            float* o = &g_t[b*Hq + tid*4];
            atomicAdd(o+0, acc[b].x); atomicAdd(o+1, acc[b].y);
            atomicAdd(o+2, acc[b].z); atomicAdd(o+3, acc[b].w);
        }
    } else {
        if (tid < 128) {
            int hl = tid >> 3, br = tid & 7;
            xa[hl][br] = g_xsum[br*Hq + hc + hl];
        }
        __syncthreads();
        float4 acc[8];
        #pragma unroll
        for (int br = 0; br < 8; br++) acc[br] = make_float4(0.f,0.f,0.f,0.f);
        const float4* W4 = (const float4*)Wv;
        #pragma unroll
        for (int hl = 0; hl < 16; hl++) {
            float4 w = W4[(size_t)(hc + hl) * 256 + tid];
            #pragma unroll
            for (int br = 0; br < 8; br++) {
                float xv = xa[hl][br];
                acc[br].x += xv*w.x; acc[br].y += xv*w.y; acc[br].z += xv*w.z; acc[br].w += xv*w.w;
            }
        }
        #pragma unroll
        for (int br = 0; br < 8; br++) {
            float* o = &g_vsum[br*Hq + tid*4];
            atomicAdd(o+0, acc[br].x); atomicAdd(o+1, acc[br].y);
            atomicAdd(o+2, acc[br].z); atomicAdd(o+3, acc[br].w);
        }
    }
}

// ================= k_pdiff: warp-per-Wq-row, front-batched loads =================
__global__ void __launch_bounds__(256)
k_pdiff(const float* __restrict__ Wq, const float* __restrict__ bq) {
    __shared__ float st[Bq*Hq];          // t staged, 16KB
    int tid = threadIdx.x;
    for (int i = tid; i < Bq*Hq; i += 256) st[i] = g_t[i];
    __syncthreads();

    int warp = tid >> 5, lane = tid & 31;
    int wg = blockIdx.x * 8 + warp;

    if (wg < 1024) {
        int h = wg;
        const float4* wr = (const float4*)(Wq + (size_t)h * Hq);
        float4 w[8];
        #pragma unroll
        for (int j = 0; j < 8; j++) w[j] = wr[j*32 + lane];

        float acc[Bq][8];
        #pragma unroll
        for (int b = 0; b < Bq; b++) {
            const float4* tb = (const float4*)&st[b*Hq];
            #pragma unroll
            for (int j = 0; j < 8; j++) {
                float4 tv = tb[j*32 + lane];     // head n = 2j + (lane>>4)
                acc[b][j] = w[j].x*tv.x + w[j].y*tv.y + w[j].z*tv.z + w[j].w*tv.w;
            }
        }
        #pragma unroll
        for (int b = 0; b < Bq; b++)
            #pragma unroll
            for (int j = 0; j < 8; j++) {
                float v = acc[b][j];
                v += __shfl_xor_sync(0xffffffffu, v, 8);
                v += __shfl_xor_sync(0xffffffffu, v, 4);
                v += __shfl_xor_sync(0xffffffffu, v, 2);
                v += __shfl_xor_sync(0xffffffffu, v, 1);
                acc[b][j] = v;
            }
        if ((lane & 15) == 0) {
            int half = lane >> 4;
            #pragma unroll
            for (int b = 0; b < Bq; b++)
                #pragma unroll
                for (int j = 0; j < 8; j++)
                    g_pdiff[(b*NHq + (2*j + half))*Hq + h] = SCALEq * acc[b][j];
        }
    } else if (wg < 1024 + Bq*NHq) {
        int id = wg - 1024;
        int b = id >> 4, n = id & 15;
        float s = bq[n*Dq + lane]      * st[b*Hq + n*Dq + lane]
                + bq[n*Dq + 32 + lane] * st[b*Hq + n*Dq + 32 + lane];
        #pragma unroll
        for (int o = 16; o > 0; o >>= 1) s += __shfl_xor_sync(0xffffffffu, s, o);
        if (lane == 0) g_bdiff[b*NHq + n] = SCALEq * s;
    }
}

// ================= k_main: scalar f32, 256 thr, 16 warps/SM, 4 rows/warp =================
#define SMEM_MAIN ((NHq*Hq + 2*Hq + 16) * sizeof(float))
__global__ void __launch_bounds__(256, 2)
k_main(const float* __restrict__ x, float* __restrict__ out) {
    extern __shared__ float sm[];
    float* sPd = sm;                 // [16][1024]
    float* sV0 = sm + NHq*Hq;        // [1024]
    float* sV1 = sV0 + Hq;           // [1024]
    float* sBd = sV1 + Hq;           // [16]

    int b = blockIdx.y, tid = threadIdx.x;
    {
        const float4* gp4 = (const float4*)&g_pdiff[b*NHq*Hq];
        float4* sp4 = (float4*)sPd;
        for (int i = tid; i < NHq*Hq/4; i += 256) sp4[i] = gp4[i];
        const float4* v0g = (const float4*)&g_vsum[(b*Rq + 0)*Hq];
        const float4* v1g = (const float4*)&g_vsum[(b*Rq + 1)*Hq];
        float4* s04 = (float4*)sV0; float4* s14 = (float4*)sV1;
        for (int i = tid; i < Hq/4; i += 256) { s04[i] = v0g[i]; s14[i] = v1g[i]; }
        if (tid < NHq) sBd[tid] = g_bdiff[b*NHq + tid];
    }
    __syncthreads();

    int warp = tid >> 5, lane = tid & 31;
    int r0 = blockIdx.x * 32 + warp * 4;           // 8 warps * 4 rows = 32 rows/block
    const float* xb = x + (size_t)b * Sq * Hq;
    float* ob = out + (size_t)b * Sq * Hq;

    const float4* xr4[4];
    #pragma unroll
    for (int i = 0; i < 4; i++)
        xr4[i] = (const float4*)(xb + (size_t)(r0 + i) * Hq);
    const float4* sPd4 = (const float4*)sPd;

    float acc[4][NHq];
    #pragma unroll
    for (int i = 0; i < 4; i++)
        #pragma unroll
        for (int n = 0; n < NHq; n++) acc[i][n] = 0.f;

    float4 xv[4];
    #pragma unroll
    for (int i = 0; i < 4; i++) xv[i] = xr4[i][lane];

    #pragma unroll
    for (int j = 0; j < 8; j++) {               // 8 * 32 lanes * float4 = 1024 h
        int h4 = lane + 32*j;
        float4 xn[4];
        if (j < 7) {
            #pragma unroll
            for (int i = 0; i < 4; i++) xn[i] = xr4[i][h4 + 32];
        }
        #pragma unroll
        for (int n = 0; n < NHq; n++) {
            float4 pd = sPd4[n*256 + h4];
            #pragma unroll
            for (int i = 0; i < 4; i++) {
                acc[i][n] += xv[i].x*pd.x + xv[i].y*pd.y + xv[i].z*pd.z + xv[i].w*pd.w;
            }
        }
        #pragma unroll
        for (int i = 0; i < 4; i++) xv[i] = xn[i];
    }

    // warp-reduce all 64 partials (butterfly -> every lane has full sums)
    #pragma unroll
    for (int i = 0; i < 4; i++)
        #pragma unroll
        for (int n = 0; n < NHq; n++) {
            float v = acc[i][n];
            v += __shfl_xor_sync(0xffffffffu, v, 16);
            v += __shfl_xor_sync(0xffffffffu, v, 8);
            v += __shfl_xor_sync(0xffffffffu, v, 4);
            v += __shfl_xor_sync(0xffffffffu, v, 2);
            v += __shfl_xor_sync(0xffffffffu, v, 1);
            acc[i][n] = 1.f / (1.f + __expf(-(v + sBd[n])));   // prob for y=0
        }

    const float4* v04 = (const float4*)sV0;
    const float4* v14 = (const float4*)sV1;
    #pragma unroll
    for (int i = 0; i < 4; i++) {
        float4* o4 = (float4*)(ob + (size_t)(r0 + i) * Hq);
        #pragma unroll
        for (int j = 0; j < 8; j++) {
            int h4 = lane + 32*j;                  // float4 index; head = h4>>4
            float ppA = acc[i][2*j];               // lane < 16 half
            float ppB = acc[i][2*j + 1];           // lane >= 16 half
            float pp = (lane & 16) ? ppB : ppA;
            float4 a = v04[h4];
            float4 c = v14[h4];
            float4 o;
            o.x = c.x + pp * (a.x - c.x);
            o.y = c.y + pp * (a.y - c.y);
            o.z = c.z + pp * (a.z - c.z);
            o.w = c.w + pp * (a.w - c.w);
            o4[h4] = o;
        }
    }
}

extern "C" void kernel_launch(void* const* d_in, const int* in_sizes, int n_in,
                              void* d_out, int out_size) {
    const float* x  = (const float*)d_in[0];
    // d_in[1] attention_mask: unused by reference
    const float* Wq = (const float*)d_in[2];
    const float* bq = (const float*)d_in[3];
    const float* Wk = (const float*)d_in[4];
    // d_in[5] bk cancels in the score difference
    const float* Wv = (const float*)d_in[6];
    const float* bv = (const float*)d_in[7];
    const int* idx  = (const int*)d_in[8];
    float* out = (float*)d_out;

    cudaFuncSetAttribute(k_main, cudaFuncAttributeMaxDynamicSharedMemorySize, (int)SMEM_MAIN);

    k_hist<<<Bq, 512>>>(idx, bv);
    k_xsum<<<dim3(SCHUNKS, Bq), 256>>>(x);
    k_proj<<<dim3(64, 2), 256>>>(Wk, Wv);
    k_pdiff<<<136, 256>>>(Wq, bq);
    k_main<<<dim3(Sq/32, Bq), 256, SMEM_MAIN>>>(x, out);
}